// round 9
// baseline (speedup 1.0000x reference)
#include <cuda_runtime.h>
#include <cstdint>

// LSTM extractor, persistent per-batch-block kernel.
//   B=2048, T=256, D=32, H=256, 4H=1024, F=256
// 128 CTAs x 256 threads; CTA owns 16 batch rows for the whole recurrence
// (LSTM rows are independent -> no grid sync needed).
// Thread u owns hidden unit u: gate columns (u, u+256, u+512, u+768).
// Weights pre-transposed to k-major gate-quads WQ[k][u] = float4(Wi,Wf,Wg,Wo)
// so warp LDG.128 is fully coalesced. Batch rows processed in packed f32x2
// pairs via fma.rn.f32x2 (2x fp32 fma throughput on sm_103a).

#define KDIM 288   // 32 (x) + 256 (h)
#define HGQ  256   // hidden units == threads per CTA
#define BPC  16    // batch rows per CTA
#define NP   8     // batch pairs per CTA

__device__ float4 g_WQ[KDIM * HGQ];      // 1.18 MB, k-major gate quads
__device__ float  g_WFCT[256 * 256];     // W_fc transposed [k][f]

__device__ __forceinline__ unsigned long long pack2(float lo, float hi) {
    unsigned long long r;
    asm("mov.b64 %0, {%1, %2};" : "=l"(r) : "f"(lo), "f"(hi));
    return r;
}
__device__ __forceinline__ float2 unpack2(unsigned long long v) {
    float2 r;
    asm("mov.b64 {%0, %1}, %2;" : "=f"(r.x), "=f"(r.y) : "l"(v));
    return r;
}
#define FMA2(acc, a, b) \
    asm("fma.rn.f32x2 %0, %1, %2, %0;" : "+l"(acc) : "l"(a), "l"(b))

__device__ __forceinline__ float sigf(float x) {
    return __fdividef(1.0f, 1.0f + __expf(-x));
}
__device__ __forceinline__ float tanhfast(float x) {
    return __fdividef(2.0f, 1.0f + __expf(-2.0f * x)) - 1.0f;
}

// ---------------- prep: transpose weights into k-major layouts ------------
__global__ void prep_kernel(const float* __restrict__ W_ih,
                            const float* __restrict__ W_hh,
                            const float* __restrict__ W_fc) {
    int blk = blockIdx.x;
    int u = threadIdx.x;  // 0..255
    if (blk < KDIM) {
        int k = blk;
        float4 q;
        if (k < 32) {
            q.x = W_ih[(u        ) * 32 + k];
            q.y = W_ih[(u + 256  ) * 32 + k];
            q.z = W_ih[(u + 512  ) * 32 + k];
            q.w = W_ih[(u + 768  ) * 32 + k];
        } else {
            int kk = k - 32;
            q.x = W_hh[(u        ) * 256 + kk];
            q.y = W_hh[(u + 256  ) * 256 + kk];
            q.z = W_hh[(u + 512  ) * 256 + kk];
            q.w = W_hh[(u + 768  ) * 256 + kk];
        }
        g_WQ[k * HGQ + u] = q;
    } else {
        int k = blk - KDIM;  // 0..255
        g_WFCT[k * 256 + u] = W_fc[u * 256 + k];
    }
}

// ---------------- main persistent LSTM + FC kernel ------------------------
__global__ void __launch_bounds__(256, 1)
lstm_kernel(const float* __restrict__ obs,
            const float* __restrict__ b_ih,
            const float* __restrict__ b_hh,
            const float* __restrict__ b_fc,
            float* __restrict__ out) {
    // hx rows: [0..31] = x_t pairs, [32..287] = h_{t-1} pairs.
    // Padded row stride 9 (72B) to soften STS bank conflicts.
    __shared__ unsigned long long hx[KDIM][9];

    const int u  = threadIdx.x;           // hidden unit / gate quad id
    const int b0 = blockIdx.x * BPC;      // first batch row of this CTA

    // biases for my 4 gate columns, pre-packed
    const float bi = b_ih[u      ] + b_hh[u      ];
    const float bf = b_ih[u + 256] + b_hh[u + 256];
    const float bg = b_ih[u + 512] + b_hh[u + 512];
    const float bo = b_ih[u + 768] + b_hh[u + 768];
    const unsigned long long bi2 = pack2(bi, bi);
    const unsigned long long bf2 = pack2(bf, bf);
    const unsigned long long bg2 = pack2(bg, bg);
    const unsigned long long bo2 = pack2(bo, bo);

    // zero smem (h region needs it; x region gets overwritten each step)
    for (int idx = u; idx < KDIM * 9; idx += 256)
        (&hx[0][0])[idx] = 0ull;
    __syncthreads();

    float c[BPC];
#pragma unroll
    for (int i = 0; i < BPC; i++) c[i] = 0.0f;

    const float* obs_cta = obs + (size_t)b0 * (256 * 32);
    const int pr = u >> 5;   // batch pair for x-staging
    const int d  = u & 31;   // input feature for x-staging

    const float4* __restrict__ wq = g_WQ;

    for (int t = 0; t < 256; t++) {
        // stage x_t as batch pairs (coalesced 128B rows)
        float x0 = obs_cta[(2 * pr    ) * 8192 + t * 32 + d];
        float x1 = obs_cta[(2 * pr + 1) * 8192 + t * 32 + d];
        hx[d][pr] = pack2(x0, x1);
        __syncthreads();   // x + previous h visible to everyone

        unsigned long long ai[NP], af[NP], ag[NP], ao[NP];
#pragma unroll
        for (int p = 0; p < NP; p++) {
            ai[p] = bi2; af[p] = bf2; ag[p] = bg2; ao[p] = bo2;
        }

        // z[b, quad(u)] += hx[b][k] * WQ[k][u], k over [x | h]
#pragma unroll 4
        for (int k = 0; k < KDIM; k++) {
            float4 w = __ldg(&wq[k * HGQ + u]);
            unsigned long long wi2 = pack2(w.x, w.x);
            unsigned long long wf2 = pack2(w.y, w.y);
            unsigned long long wg2 = pack2(w.z, w.z);
            unsigned long long wo2 = pack2(w.w, w.w);
#pragma unroll
            for (int p = 0; p < NP; p++) {
                unsigned long long h2 = hx[k][p];  // LDS.64 broadcast
                FMA2(ai[p], h2, wi2);
                FMA2(af[p], h2, wf2);
                FMA2(ag[p], h2, wg2);
                FMA2(ao[p], h2, wo2);
            }
        }
        __syncthreads();   // everyone done reading hx before h overwrite

        // gates + state update (registers only), then publish new h
#pragma unroll
        for (int p = 0; p < NP; p++) {
            float2 zi = unpack2(ai[p]);
            float2 zf = unpack2(af[p]);
            float2 zg = unpack2(ag[p]);
            float2 zo = unpack2(ao[p]);

            float i0 = sigf(zi.x), f0 = sigf(zf.x);
            float g0 = tanhfast(zg.x), o0 = sigf(zo.x);
            c[2 * p] = f0 * c[2 * p] + i0 * g0;
            float h0 = o0 * tanhfast(c[2 * p]);

            float i1 = sigf(zi.y), f1 = sigf(zf.y);
            float g1 = tanhfast(zg.y), o1 = sigf(zo.y);
            c[2 * p + 1] = f1 * c[2 * p + 1] + i1 * g1;
            float h1 = o1 * tanhfast(c[2 * p + 1]);

            hx[32 + u][p] = pack2(h0, h1);
        }
    }
    __syncthreads();   // final h published

    // FC: out[b][u] = sum_k h[b][k] * W_fc[u][k] + b_fc[u]
    unsigned long long afc[NP];
#pragma unroll
    for (int p = 0; p < NP; p++) afc[p] = 0ull;

    const float* __restrict__ wfct = g_WFCT;
#pragma unroll 4
    for (int k = 0; k < 256; k++) {
        float wv = __ldg(&wfct[k * 256 + u]);  // coalesced
        unsigned long long w2 = pack2(wv, wv);
#pragma unroll
        for (int p = 0; p < NP; p++) {
            unsigned long long h2 = hx[32 + k][p];
            FMA2(afc[p], h2, w2);
        }
    }
    const float bb = b_fc[u];
#pragma unroll
    for (int p = 0; p < NP; p++) {
        float2 r = unpack2(afc[p]);
        out[(size_t)(b0 + 2 * p    ) * 256 + u] = r.x + bb;
        out[(size_t)(b0 + 2 * p + 1) * 256 + u] = r.y + bb;
    }
}

extern "C" void kernel_launch(void* const* d_in, const int* in_sizes, int n_in,
                              void* d_out, int out_size) {
    const float* obs  = (const float*)d_in[0];  // [2048,256,32]
    const float* W_ih = (const float*)d_in[1];  // [1024,32]
    const float* W_hh = (const float*)d_in[2];  // [1024,256]
    const float* b_ih = (const float*)d_in[3];  // [1024]
    const float* b_hh = (const float*)d_in[4];  // [1024]
    const float* W_fc = (const float*)d_in[5];  // [256,256]
    const float* b_fc = (const float*)d_in[6];  // [256]
    float* out = (float*)d_out;                 // [2048,256]

    prep_kernel<<<KDIM + 256, 256>>>(W_ih, W_hh, W_fc);
    lstm_kernel<<<128, 256>>>(obs, b_ih, b_hh, b_fc, out);
}

// round 10
// speedup vs baseline: 1.0569x; 1.0569x over previous
#include <cuda_runtime.h>
#include <cstdint>

// LSTM extractor: B=2048, T=256, D=32, H=256, F=256.
// 152 CTAs x 512 threads. CTA owns 12-14 batch rows (as f32x2 pairs) for the
// whole recurrence (rows independent -> no grid sync).
// Gate split: warps 0-7 (group A) compute gates i,f + own c/h update;
// warps 8-15 (group B) compute gates g,o and hand tanh(g), sigm(o) to A via
// smem. Weight reads are partitioned between groups (no traffic duplication).
// Batch pairs processed with packed fma.rn.f32x2 (2x fp32 fma rate).

#define KDIM 288   // 32 (x) + 256 (h)
#define NP   7     // max batch pairs per CTA (some CTAs use 6)
#define NCTA 152
#define NFULL 112  // CTAs with 7 pairs; rest have 6  (112*7 + 40*6 = 1024)

__device__ float2 g_Wif[KDIM * 256];   // (W_i[u][k], W_f[u][k]) k-major
__device__ float2 g_Wgo[KDIM * 256];   // (W_g[u][k], W_o[u][k]) k-major
__device__ float  g_WFCT[256 * 256];   // W_fc transposed [k][f]

typedef unsigned long long u64;

__device__ __forceinline__ u64 pack2(float lo, float hi) {
    u64 r;
    asm("mov.b64 %0, {%1, %2};" : "=l"(r) : "f"(lo), "f"(hi));
    return r;
}
__device__ __forceinline__ float2 unpack2(u64 v) {
    float2 r;
    asm("mov.b64 {%0, %1}, %2;" : "=f"(r.x), "=f"(r.y) : "l"(v));
    return r;
}
#define FMA2(acc, a, b) \
    asm("fma.rn.f32x2 %0, %1, %2, %0;" : "+l"(acc) : "l"(a), "l"(b))

__device__ __forceinline__ float sigf(float x) {
    return __fdividef(1.0f, 1.0f + __expf(-x));
}
__device__ __forceinline__ float tanhfast(float x) {
    return __fdividef(2.0f, 1.0f + __expf(-2.0f * x)) - 1.0f;
}

// ---------------- prep: weights -> k-major gate-pair layouts --------------
__global__ void prep_kernel(const float* __restrict__ W_ih,
                            const float* __restrict__ W_hh,
                            const float* __restrict__ W_fc) {
    int blk = blockIdx.x;
    int u = threadIdx.x;  // 0..255
    if (blk < KDIM) {
        int k = blk;
        float wi, wf, wg, wo;
        if (k < 32) {
            wi = W_ih[(u      ) * 32 + k];
            wf = W_ih[(u + 256) * 32 + k];
            wg = W_ih[(u + 512) * 32 + k];
            wo = W_ih[(u + 768) * 32 + k];
        } else {
            int kk = k - 32;
            wi = W_hh[(u      ) * 256 + kk];
            wf = W_hh[(u + 256) * 256 + kk];
            wg = W_hh[(u + 512) * 256 + kk];
            wo = W_hh[(u + 768) * 256 + kk];
        }
        g_Wif[k * 256 + u] = make_float2(wi, wf);
        g_Wgo[k * 256 + u] = make_float2(wg, wo);
    } else {
        int k = blk - KDIM;  // 0..255
        g_WFCT[k * 256 + u] = W_fc[u * 256 + k];
    }
}

// ---------------- main persistent LSTM + FC kernel ------------------------
__global__ void __launch_bounds__(512, 1)
lstm_kernel(const float* __restrict__ obs,
            const float* __restrict__ b_ih,
            const float* __restrict__ b_hh,
            const float* __restrict__ b_fc,
            float* __restrict__ out) {
    // hx rows: [0..31] = x_t pairs, [32..287] = h_{t-1} pairs; stride 8 u64
    // (64B) so LDS.128 on pairs {0,1},{2,3},{4,5} is aligned.
    __shared__ u64 hx[KDIM][8];          // 18.4 KB
    __shared__ u64 bufg[256][NP];        // tanh(g) pairs, 14.3 KB
    __shared__ u64 bufo[256][NP];        // sigm(o) pairs, 14.3 KB

    const int tid = threadIdx.x;
    const int grp = tid >> 8;            // 0: gates i,f (+c/h); 1: gates g,o
    const int u   = tid & 255;
    const int bid = blockIdx.x;

    const int valid = (bid < NFULL) ? 7 : 6;
    const int pb    = (bid < NFULL) ? 7 * bid : 7 * NFULL + 6 * (bid - NFULL);

    // biases for my two gate columns, pre-packed
    const int g0 = u + grp * 512;            // i (grp0) / g (grp1)
    const int g1 = u + grp * 512 + 256;      // f (grp0) / o (grp1)
    const u64 b02 = pack2(b_ih[g0] + b_hh[g0], b_ih[g0] + b_hh[g0]);
    const u64 b12 = pack2(b_ih[g1] + b_hh[g1], b_ih[g1] + b_hh[g1]);

    // zero hx (h region + pad must start at 0)
    for (int idx = tid; idx < KDIM * 8; idx += 512)
        (&hx[0][0])[idx] = 0ull;

    float cc[2 * NP];
#pragma unroll
    for (int i = 0; i < 2 * NP; i++) cc[i] = 0.0f;

    const float2* __restrict__ wp = grp ? g_Wgo : g_Wif;

    // x-staging role (group A threads 0..223): pair pr, feature d
    const int pr = tid >> 5;       // 0..6 for tid<224
    const int d  = tid & 31;
    const int pr_eff = (pr < valid) ? pr : (valid - 1);
    const float* xsrc = obs + (size_t)(2 * (pb + pr_eff)) * 8192 + d;

    // stage x(0)
    if (tid < 224) {
        hx[d][pr] = pack2(xsrc[0], xsrc[8192]);
    }
    __syncthreads();

    for (int t = 0; t < 256; t++) {
        u64 a0[NP], a1[NP];
#pragma unroll
        for (int p = 0; p < NP; p++) { a0[p] = b02; a1[p] = b12; }

        // z[b, gate(u)] += hx[b][k] * W[gate][k][u]
#pragma unroll 4
        for (int k = 0; k < KDIM; k++) {
            float2 w = __ldg(&wp[k * 256 + u]);
            u64 w0 = pack2(w.x, w.x);
            u64 w1 = pack2(w.y, w.y);
            ulonglong2 h01 = *(const ulonglong2*)&hx[k][0];
            ulonglong2 h23 = *(const ulonglong2*)&hx[k][2];
            ulonglong2 h45 = *(const ulonglong2*)&hx[k][4];
            u64        h6  = hx[k][6];
            FMA2(a0[0], h01.x, w0); FMA2(a1[0], h01.x, w1);
            FMA2(a0[1], h01.y, w0); FMA2(a1[1], h01.y, w1);
            FMA2(a0[2], h23.x, w0); FMA2(a1[2], h23.x, w1);
            FMA2(a0[3], h23.y, w0); FMA2(a1[3], h23.y, w1);
            FMA2(a0[4], h45.x, w0); FMA2(a1[4], h45.x, w1);
            FMA2(a0[5], h45.y, w0); FMA2(a1[5], h45.y, w1);
            FMA2(a0[6], h6,    w0); FMA2(a1[6], h6,    w1);
        }

        if (grp == 1) {
            // publish tanh(g), sigm(o)
#pragma unroll
            for (int p = 0; p < NP; p++) {
                float2 zg = unpack2(a0[p]);
                float2 zo = unpack2(a1[p]);
                bufg[u][p] = pack2(tanhfast(zg.x), tanhfast(zg.y));
                bufo[u][p] = pack2(sigf(zo.x),     sigf(zo.y));
            }
        }
        __syncthreads();   // buf visible; everyone done reading hx

        if (grp == 0) {
            // c/h update, publish new h
#pragma unroll
            for (int p = 0; p < NP; p++) {
                float2 zi = unpack2(a0[p]);
                float2 zf = unpack2(a1[p]);
                float2 tg = unpack2(bufg[u][p]);
                float2 so = unpack2(bufo[u][p]);

                float c0 = sigf(zf.x) * cc[2 * p]     + sigf(zi.x) * tg.x;
                float c1 = sigf(zf.y) * cc[2 * p + 1] + sigf(zi.y) * tg.y;
                cc[2 * p]     = c0;
                cc[2 * p + 1] = c1;
                float h0 = so.x * tanhfast(c0);
                float h1 = so.y * tanhfast(c1);
                hx[32 + u][p] = pack2(h0, h1);
            }
            // stage x(t+1)
            if (t < 255 && tid < 224) {
                const float* xs = xsrc + (size_t)(t + 1) * 32;
                hx[d][pr] = pack2(xs[0], xs[8192]);
            }
        }
        __syncthreads();   // new h + x visible before next GEMM
    }

    // FC: out[b][u] = sum_k h[b][k] * W_fc[u][k] + b_fc[u]   (group A only)
    if (grp == 0) {
        u64 afc[NP];
#pragma unroll
        for (int p = 0; p < NP; p++) afc[p] = 0ull;

        const float* __restrict__ wfct = g_WFCT;
#pragma unroll 4
        for (int k = 0; k < 256; k++) {
            float wv = __ldg(&wfct[k * 256 + u]);  // coalesced
            u64 w2 = pack2(wv, wv);
            ulonglong2 h01 = *(const ulonglong2*)&hx[32 + k][0];
            ulonglong2 h23 = *(const ulonglong2*)&hx[32 + k][2];
            ulonglong2 h45 = *(const ulonglong2*)&hx[32 + k][4];
            u64        h6  = hx[32 + k][6];
            FMA2(afc[0], h01.x, w2);
            FMA2(afc[1], h01.y, w2);
            FMA2(afc[2], h23.x, w2);
            FMA2(afc[3], h23.y, w2);
            FMA2(afc[4], h45.x, w2);
            FMA2(afc[5], h6,    w2);   // placeholder order fixed below
            FMA2(afc[6], h45.y, w2);
        }
        // NOTE: afc[5] accumulated h45.y? keep mapping consistent:
        // afc index -> pair: 0,1,2,3,4 use pairs 0..4; we accumulated
        // afc[5] with h6 (pair 6) and afc[6] with h45.y (pair 5).
        const float bb = b_fc[u];
        float2 r;
        r = unpack2(afc[0]);
        out[(size_t)(2 * (pb + 0)    ) * 256 + u] = r.x + bb;
        out[(size_t)(2 * (pb + 0) + 1) * 256 + u] = r.y + bb;
        r = unpack2(afc[1]);
        out[(size_t)(2 * (pb + 1)    ) * 256 + u] = r.x + bb;
        out[(size_t)(2 * (pb + 1) + 1) * 256 + u] = r.y + bb;
        r = unpack2(afc[2]);
        out[(size_t)(2 * (pb + 2)    ) * 256 + u] = r.x + bb;
        out[(size_t)(2 * (pb + 2) + 1) * 256 + u] = r.y + bb;
        r = unpack2(afc[3]);
        out[(size_t)(2 * (pb + 3)    ) * 256 + u] = r.x + bb;
        out[(size_t)(2 * (pb + 3) + 1) * 256 + u] = r.y + bb;
        r = unpack2(afc[4]);
        out[(size_t)(2 * (pb + 4)    ) * 256 + u] = r.x + bb;
        out[(size_t)(2 * (pb + 4) + 1) * 256 + u] = r.y + bb;
        r = unpack2(afc[6]);  // pair 5
        out[(size_t)(2 * (pb + 5)    ) * 256 + u] = r.x + bb;
        out[(size_t)(2 * (pb + 5) + 1) * 256 + u] = r.y + bb;
        if (valid == 7) {
            r = unpack2(afc[5]);  // pair 6
            out[(size_t)(2 * (pb + 6)    ) * 256 + u] = r.x + bb;
            out[(size_t)(2 * (pb + 6) + 1) * 256 + u] = r.y + bb;
        }
    }
}

extern "C" void kernel_launch(void* const* d_in, const int* in_sizes, int n_in,
                              void* d_out, int out_size) {
    const float* obs  = (const float*)d_in[0];  // [2048,256,32]
    const float* W_ih = (const float*)d_in[1];  // [1024,32]
    const float* W_hh = (const float*)d_in[2];  // [1024,256]
    const float* b_ih = (const float*)d_in[3];  // [1024]
    const float* b_hh = (const float*)d_in[4];  // [1024]
    const float* W_fc = (const float*)d_in[5];  // [256,256]
    const float* b_fc = (const float*)d_in[6];  // [256]
    float* out = (float*)d_out;                 // [2048,256]

    prep_kernel<<<KDIM + 256, 256>>>(W_ih, W_hh, W_fc);
    lstm_kernel<<<NCTA, 512>>>(obs, b_ih, b_hh, b_fc, out);
}

// round 11
// speedup vs baseline: 3.1934x; 3.0215x over previous
#include <cuda_runtime.h>
#include <cuda_fp16.h>
#include <cstdint>

// LSTM extractor via warp-MMA (HMMA m16n8k16, fp16 in / fp32 accum).
//   B=2048, T=256, D=32, H=256, F=256.
// 64 CTAs x 512 threads. CTA owns M=32 batch rows for the whole recurrence.
// Warp w owns hidden units u in [16w, 16w+16): columns {u, u+256, u+512,
// u+768} = 8 n8-tiles per M-tile. C-fragments of all 4 gates for the same
// (row,u) land in the SAME thread -> gate fusion + c-state in registers.
// Weights pre-swizzled (prep kernel) into per-thread fragment order, fp16,
// so B loads are coalesced LDG.128. A (x|h) is fp16 in smem, ldmatrix.x4.

#define NKC     18      // K chunks of 16 (K = 288 = 32 x + 256 h)
#define ASTRIDE 296     // halves per A row (592B = 37*16, conflict-free)
#define NWARP   16
#define NCTA    64      // 2048 / 32 rows

__device__ uint4 g_Wfrag[NWARP * NKC * 4 * 32];   // 36864 uint4 (576 KB)
__device__ uint4 g_WfcFrag[NWARP * 16 * 32];      // 8192 uint4 (128 KB)

__device__ __forceinline__ float tanhap(float x) {
    float r;
    asm("tanh.approx.f32 %0, %1;" : "=f"(r) : "f"(x));
    return r;
}
__device__ __forceinline__ float sigap(float x) {
    return fmaf(tanhap(0.5f * x), 0.5f, 0.5f);
}

__device__ __forceinline__ uint32_t smemu32(const void* p) {
    uint32_t a;
    asm("{ .reg .u64 t; cvta.to.shared.u64 t, %1; cvt.u32.u64 %0, t; }"
        : "=r"(a) : "l"(p));
    return a;
}

#define LDMATRIX_X4(a0, a1, a2, a3, addr)                                   \
    asm volatile("ldmatrix.sync.aligned.m8n8.x4.shared.b16 {%0,%1,%2,%3}, [%4];" \
                 : "=r"(a0), "=r"(a1), "=r"(a2), "=r"(a3) : "r"(addr))

#define MMA16816(d, a0, a1, a2, a3, b0, b1)                                 \
    asm volatile("mma.sync.aligned.m16n8k16.row.col.f32.f16.f16.f32 "       \
                 "{%0,%1,%2,%3},{%4,%5,%6,%7},{%8,%9},{%0,%1,%2,%3};"       \
                 : "+f"(d[0]), "+f"(d[1]), "+f"(d[2]), "+f"(d[3])           \
                 : "r"(a0), "r"(a1), "r"(a2), "r"(a3), "r"(b0), "r"(b1))

// ---------------- prep: weights -> fp16 fragment-major layouts ------------
__device__ __forceinline__ float wval(const float* W_ih, const float* W_hh,
                                      int col, int k) {
    return (k < 32) ? W_ih[col * 32 + k] : W_hh[col * 256 + (k - 32)];
}

__global__ void prep_kernel(const float* __restrict__ W_ih,
                            const float* __restrict__ W_hh,
                            const float* __restrict__ W_fc) {
    int g = blockIdx.x * 256 + threadIdx.x;
    union { __half h[8]; uint4 v; } u;
    if (g < NWARP * NKC * 4 * 32) {
        int l = g & 31;
        int t = g >> 5;
        int q = t & 3;  t >>= 2;
        int kc = t % NKC;
        int w  = t / NKC;
        int k0 = kc * 16 + (l & 3) * 2;
        int n  = l >> 2;
        for (int s = 0; s < 2; s++) {
            int tt = 2 * q + s;
            int gate = tt >> 1, ut = tt & 1;
            int col = gate * 256 + w * 16 + ut * 8 + n;
            u.h[s * 4 + 0] = __float2half(wval(W_ih, W_hh, col, k0));
            u.h[s * 4 + 1] = __float2half(wval(W_ih, W_hh, col, k0 + 1));
            u.h[s * 4 + 2] = __float2half(wval(W_ih, W_hh, col, k0 + 8));
            u.h[s * 4 + 3] = __float2half(wval(W_ih, W_hh, col, k0 + 9));
        }
        g_Wfrag[g] = u.v;
    } else if (g < NWARP * NKC * 4 * 32 + NWARP * 16 * 32) {
        int g2 = g - NWARP * NKC * 4 * 32;
        int l = g2 & 31;
        int t = g2 >> 5;
        int kc = t & 15;
        int w  = t >> 4;
        int k0 = kc * 16 + (l & 3) * 2;
        int n  = l >> 2;
        for (int s = 0; s < 2; s++) {            // ut = s
            int col = w * 16 + s * 8 + n;        // output feature
            u.h[s * 4 + 0] = __float2half(W_fc[col * 256 + k0]);
            u.h[s * 4 + 1] = __float2half(W_fc[col * 256 + k0 + 1]);
            u.h[s * 4 + 2] = __float2half(W_fc[col * 256 + k0 + 8]);
            u.h[s * 4 + 3] = __float2half(W_fc[col * 256 + k0 + 9]);
        }
        g_WfcFrag[g2] = u.v;
    }
}

// ---------------- main persistent LSTM + FC kernel ------------------------
__global__ void __launch_bounds__(512, 1)
lstm_kernel(const float* __restrict__ obs,
            const float* __restrict__ b_ih,
            const float* __restrict__ b_hh,
            const float* __restrict__ b_fc,
            float* __restrict__ out) {
    __shared__ __align__(16) __half hA[32 * ASTRIDE];   // A = [x(32) | h(256)]
    __shared__ float bias_s[1024];

    const int tid  = threadIdx.x;
    const int w    = tid >> 5;
    const int l    = tid & 31;
    const int gid  = l >> 2;       // row group within tile
    const int tid4 = l & 3;        // col pair within tile
    const int b0   = blockIdx.x * 32;

    bias_s[tid]       = b_ih[tid]       + b_hh[tid];
    bias_s[tid + 512] = b_ih[tid + 512] + b_hh[tid + 512];

    for (int i = tid; i < 32 * ASTRIDE; i += 512)
        hA[i] = __float2half(0.0f);
    __syncthreads();

    // stage x(0): thread -> (row, feature pair)
    const int xrow = tid >> 4;
    const int xdp  = (tid & 15) * 2;
    const float* xptr = obs + (size_t)(b0 + xrow) * 8192 + xdp;
    {
        float2 x2 = *(const float2*)xptr;
        *(__half2*)&hA[xrow * ASTRIDE + xdp] = __float22half2_rn(x2);
    }
    __syncthreads();

    float c[16];
#pragma unroll
    for (int i = 0; i < 16; i++) c[i] = 0.0f;

    const uint4* __restrict__ wbase = g_Wfrag + w * (NKC * 4 * 32) + l;
    const uint32_t aAddr =
        smemu32(hA) + (uint32_t)(((l & 15) * ASTRIDE + (l >> 4) * 8) * 2);

    for (int t = 0; t < 256; t++) {
        float acc[2][8][4];
#pragma unroll
        for (int tt = 0; tt < 8; tt++) {
            int gate = tt >> 1, ut = tt & 1;
            float2 bs = *(const float2*)
                &bias_s[gate * 256 + w * 16 + ut * 8 + tid4 * 2];
#pragma unroll
            for (int mt = 0; mt < 2; mt++) {
                acc[mt][tt][0] = bs.x; acc[mt][tt][1] = bs.y;
                acc[mt][tt][2] = bs.x; acc[mt][tt][3] = bs.y;
            }
        }

#pragma unroll 2
        for (int kc = 0; kc < NKC; kc++) {
            uint4 B0 = __ldg(wbase + (kc * 4 + 0) * 32);
            uint4 B1 = __ldg(wbase + (kc * 4 + 1) * 32);
            uint4 B2 = __ldg(wbase + (kc * 4 + 2) * 32);
            uint4 B3 = __ldg(wbase + (kc * 4 + 3) * 32);
#pragma unroll
            for (int mt = 0; mt < 2; mt++) {
                uint32_t a0, a1, a2, a3;
                LDMATRIX_X4(a0, a1, a2, a3,
                            aAddr + (uint32_t)((mt * 16 * ASTRIDE + kc * 16) * 2));
                MMA16816(acc[mt][0], a0, a1, a2, a3, B0.x, B0.y);
                MMA16816(acc[mt][1], a0, a1, a2, a3, B0.z, B0.w);
                MMA16816(acc[mt][2], a0, a1, a2, a3, B1.x, B1.y);
                MMA16816(acc[mt][3], a0, a1, a2, a3, B1.z, B1.w);
                MMA16816(acc[mt][4], a0, a1, a2, a3, B2.x, B2.y);
                MMA16816(acc[mt][5], a0, a1, a2, a3, B2.z, B2.w);
                MMA16816(acc[mt][6], a0, a1, a2, a3, B3.x, B3.y);
                MMA16816(acc[mt][7], a0, a1, a2, a3, B3.z, B3.w);
            }
        }
        __syncthreads();   // all warps done reading hA (x_t | h_t)

        // gates + state update; publish h_{t+1}
#pragma unroll
        for (int mt = 0; mt < 2; mt++) {
#pragma unroll
            for (int ut = 0; ut < 2; ut++) {
#pragma unroll
                for (int jr = 0; jr < 2; jr++) {      // row half (j = 2*jr)
                    int j = 2 * jr;
                    int ci = (mt * 2 + ut) * 4 + j;
                    float i0 = sigap(acc[mt][0 + ut][j]);
                    float i1 = sigap(acc[mt][0 + ut][j + 1]);
                    float f0 = sigap(acc[mt][2 + ut][j]);
                    float f1 = sigap(acc[mt][2 + ut][j + 1]);
                    float g0 = tanhap(acc[mt][4 + ut][j]);
                    float g1 = tanhap(acc[mt][4 + ut][j + 1]);
                    float o0 = sigap(acc[mt][6 + ut][j]);
                    float o1 = sigap(acc[mt][6 + ut][j + 1]);
                    float c0 = fmaf(f0, c[ci],     i0 * g0);
                    float c1 = fmaf(f1, c[ci + 1], i1 * g1);
                    c[ci] = c0; c[ci + 1] = c1;
                    float h0 = o0 * tanhap(c0);
                    float h1 = o1 * tanhap(c1);
                    int row = mt * 16 + gid + jr * 8;
                    int u   = w * 16 + ut * 8 + tid4 * 2;
                    *(__half2*)&hA[row * ASTRIDE + 32 + u] =
                        __floats2half2_rn(h0, h1);
                }
            }
        }

        // stage x(t+1)
        if (t < 255) {
            float2 x2 = *(const float2*)(xptr + (size_t)(t + 1) * 32);
            *(__half2*)&hA[xrow * ASTRIDE + xdp] = __float22half2_rn(x2);
        }
        __syncthreads();   // h_{t+1} + x_{t+1} visible
    }

    // ---- FC: out[b][f] = h_last . W_fc[f][:] + b_fc[f] ----
    float accf[2][2][4];
#pragma unroll
    for (int mt = 0; mt < 2; mt++)
#pragma unroll
        for (int ut = 0; ut < 2; ut++)
#pragma unroll
            for (int j = 0; j < 4; j++) accf[mt][ut][j] = 0.0f;

    const uint4* __restrict__ fbase = g_WfcFrag + w * (16 * 32) + l;
#pragma unroll 2
    for (int kc = 0; kc < 16; kc++) {
        uint4 B = __ldg(fbase + kc * 32);
#pragma unroll
        for (int mt = 0; mt < 2; mt++) {
            uint32_t a0, a1, a2, a3;
            LDMATRIX_X4(a0, a1, a2, a3,
                        aAddr + (uint32_t)((mt * 16 * ASTRIDE + 32 + kc * 16) * 2));
            MMA16816(accf[mt][0], a0, a1, a2, a3, B.x, B.y);
            MMA16816(accf[mt][1], a0, a1, a2, a3, B.z, B.w);
        }
    }

#pragma unroll
    for (int mt = 0; mt < 2; mt++) {
#pragma unroll
        for (int ut = 0; ut < 2; ut++) {
            int col = w * 16 + ut * 8 + tid4 * 2;
            float2 bf = *(const float2*)&b_fc[col];
#pragma unroll
            for (int jr = 0; jr < 2; jr++) {
                int row = b0 + mt * 16 + gid + jr * 8;
                float2 r;
                r.x = accf[mt][ut][2 * jr]     + bf.x;
                r.y = accf[mt][ut][2 * jr + 1] + bf.y;
                *(float2*)&out[(size_t)row * 256 + col] = r;
            }
        }
    }
}

extern "C" void kernel_launch(void* const* d_in, const int* in_sizes, int n_in,
                              void* d_out, int out_size) {
    const float* obs  = (const float*)d_in[0];  // [2048,256,32]
    const float* W_ih = (const float*)d_in[1];  // [1024,32]
    const float* W_hh = (const float*)d_in[2];  // [1024,256]
    const float* b_ih = (const float*)d_in[3];  // [1024]
    const float* b_hh = (const float*)d_in[4];  // [1024]
    const float* W_fc = (const float*)d_in[5];  // [256,256]
    const float* b_fc = (const float*)d_in[6];  // [256]
    float* out = (float*)d_out;                 // [2048,256]

    int total = NWARP * NKC * 4 * 32 + NWARP * 16 * 32;   // 45056
    prep_kernel<<<(total + 255) / 256, 256>>>(W_ih, W_hh, W_fc);
    lstm_kernel<<<NCTA, 512>>>(obs, b_ih, b_hh, b_fc, out);
}